// round 2
// baseline (speedup 1.0000x reference)
#include <cuda_runtime.h>
#include <stdint.h>

#define NN 100000
#define DIM 128
#define NE 600000

// Scratch (static device globals; no runtime allocation)
__device__ float g_S0[(size_t)NN * DIM];    // 51.2 MB  relation-0 feature sums
__device__ float g_S1[(size_t)NN * DIM];    // 51.2 MB  relation-1 feature sums
__device__ float g_agg[(size_t)NN * DIM];   // 51.2 MB  post-linear aggregate
__device__ float g_Wt[384 * 128];           // [k][o] transposed concat of W0|W1|Wself
__device__ float g_Ct[384 * 128];           // [seg*128+c][o] transposed conv weights
__device__ int   g_idx64;                   // 1 if edge indices are int64

// ---------------------------------------------------------------------------
__global__ void zero_kernel() {
    size_t i = (size_t)blockIdx.x * blockDim.x + threadIdx.x;
    if (i < (size_t)NN * DIM / 4) {
        ((float4*)g_S0)[i] = make_float4(0.f, 0.f, 0.f, 0.f);
        ((float4*)g_S1)[i] = make_float4(0.f, 0.f, 0.f, 0.f);
    }
}

// Detect edge-index dtype: int64 values < 2^31 have all odd 32-bit words == 0.
__global__ void detect_kernel(const int* __restrict__ e0_raw) {
    if (threadIdx.x == 0 && blockIdx.x == 0) {
        int is64 = 1;
        for (int i = 1; i < 64; i += 2)
            if (e0_raw[i] != 0) { is64 = 0; break; }
        g_idx64 = is64;
    }
}

// Transpose/concat weights once per launch (49k elements, trivial cost)
__global__ void prep_kernel(const float* __restrict__ W_rel,
                            const float* __restrict__ W_self,
                            const float* __restrict__ conv_w) {
    int t = blockIdx.x * blockDim.x + threadIdx.x;
    if (t >= 384 * 128) return;
    int k = t >> 7, o = t & 127;
    int seg = k >> 7, kl = k & 127;
    float w = (seg < 2) ? W_rel[seg * 16384 + o * 128 + kl]
                        : W_self[o * 128 + kl];
    g_Wt[k * 128 + o] = w;
    // conv_w layout [o][c][k]: Ct[seg*128 + c][o] = conv_w[o*384 + c*3 + seg]
    g_Ct[k * 128 + o] = conv_w[o * 384 + kl * 3 + seg];
}

// ---------------------------------------------------------------------------
// One warp per edge: gather 512B source row, vector-reduce into target row.
__global__ void scatter_kernel(const float* __restrict__ x,
                               const void* __restrict__ e0,
                               const void* __restrict__ e1) {
    int warp = (int)(((size_t)blockIdx.x * blockDim.x + threadIdx.x) >> 5);
    int lane = threadIdx.x & 31;
    if (warp >= 2 * NE) return;
    const void* ei;
    float* S;
    int e;
    if (warp < NE) { ei = e0; S = g_S0; e = warp; }
    else           { ei = e1; S = g_S1; e = warp - NE; }
    int src, tgt;
    if (g_idx64) {
        src = (int)((const long long*)ei)[e];
        tgt = (int)((const long long*)ei)[NE + e];
    } else {
        src = ((const int*)ei)[e];
        tgt = ((const int*)ei)[NE + e];
    }
    if ((unsigned)src >= NN || (unsigned)tgt >= NN) return;  // safety net
    float4 v = ((const float4*)(x + (size_t)src * DIM))[lane];
    float* dst = S + (size_t)tgt * DIM + lane * 4;
    asm volatile("red.global.add.v4.f32 [%0], {%1,%2,%3,%4};"
                 :: "l"(dst), "f"(v.x), "f"(v.y), "f"(v.z), "f"(v.w)
                 : "memory");
}

// ---------------------------------------------------------------------------
// SGEMM 1: agg[n, o] = sum_k [S0|S1|x][n, k] * Wcat[o, k]     (K = 384)
// 128x128 CTA tile, 8x8 per-thread micro-tile, BK = 16.
__global__ __launch_bounds__(256)
void gemm1_kernel(const float* __restrict__ x) {
    __shared__ float As[128][17];   // [row][k], padded: conflict-free
    __shared__ float Bs[16][128];   // [k][o]
    int t = threadIdx.x;
    int trow = t >> 4, tcol = t & 15;
    int row0 = blockIdx.x * 128;

    float acc[8][8];
#pragma unroll
    for (int i = 0; i < 8; i++)
#pragma unroll
        for (int j = 0; j < 8; j++) acc[i][j] = 0.f;

    for (int kt = 0; kt < 24; ++kt) {
        int seg = kt >> 3;                       // which 128-wide K segment
        const float* Ab = (seg == 0) ? g_S0 : (seg == 1 ? g_S1 : x);
        int ko = (kt & 7) * 16;
#pragma unroll
        for (int l = 0; l < 2; ++l) {
            int i = l * 256 + t;
            int row = i >> 2, kq = (i & 3) * 4;
            int gr = row0 + row;
            float4 v = make_float4(0.f, 0.f, 0.f, 0.f);
            if (gr < NN) v = *(const float4*)(Ab + (size_t)gr * DIM + ko + kq);
            As[row][kq + 0] = v.x; As[row][kq + 1] = v.y;
            As[row][kq + 2] = v.z; As[row][kq + 3] = v.w;
            float4 w = *(const float4*)(g_Wt + (kt * 16 + (i >> 5)) * 128 + (i & 31) * 4);
            *(float4*)&Bs[i >> 5][(i & 31) * 4] = w;
        }
        __syncthreads();
#pragma unroll
        for (int kk = 0; kk < 16; ++kk) {
            float a[8], b[8];
#pragma unroll
            for (int j = 0; j < 8; j++) a[j] = As[trow * 8 + j][kk];
#pragma unroll
            for (int j = 0; j < 8; j++) b[j] = Bs[kk][tcol * 8 + j];
#pragma unroll
            for (int i = 0; i < 8; i++)
#pragma unroll
                for (int j = 0; j < 8; j++)
                    acc[i][j] = fmaf(a[i], b[j], acc[i][j]);
        }
        __syncthreads();
    }
#pragma unroll
    for (int i = 0; i < 8; i++) {
        int gr = row0 + trow * 8 + i;
        if (gr < NN) {
            *(float4*)&g_agg[(size_t)gr * DIM + tcol * 8] =
                make_float4(acc[i][0], acc[i][1], acc[i][2], acc[i][3]);
            *(float4*)&g_agg[(size_t)gr * DIM + tcol * 8 + 4] =
                make_float4(acc[i][4], acc[i][5], acc[i][6], acc[i][7]);
        }
    }
}

// ---------------------------------------------------------------------------
// SGEMM 2 (= Conv1d k=3 pad=1 over node axis + bias + ReLU):
// y[n, o] = relu(b[o] + sum_{seg=0..2} sum_c conv_w[o,c,seg] * agg[n+seg-1, c])
__global__ __launch_bounds__(256)
void gemm2_kernel(float* __restrict__ out, const float* __restrict__ conv_b) {
    __shared__ float As[128][17];
    __shared__ float Bs[16][128];
    int t = threadIdx.x;
    int trow = t >> 4, tcol = t & 15;
    int row0 = blockIdx.x * 128;

    float acc[8][8];
#pragma unroll
    for (int i = 0; i < 8; i++)
#pragma unroll
        for (int j = 0; j < 8; j++) acc[i][j] = 0.f;

    for (int kt = 0; kt < 24; ++kt) {
        int seg = kt >> 3;          // tap index -> row shift seg-1
        int ko = (kt & 7) * 16;
#pragma unroll
        for (int l = 0; l < 2; ++l) {
            int i = l * 256 + t;
            int row = i >> 2, kq = (i & 3) * 4;
            int gr = row0 + row + seg - 1;
            float4 v = make_float4(0.f, 0.f, 0.f, 0.f);
            if (gr >= 0 && gr < NN)
                v = *(const float4*)(g_agg + (size_t)gr * DIM + ko + kq);
            As[row][kq + 0] = v.x; As[row][kq + 1] = v.y;
            As[row][kq + 2] = v.z; As[row][kq + 3] = v.w;
            float4 w = *(const float4*)(g_Ct + (kt * 16 + (i >> 5)) * 128 + (i & 31) * 4);
            *(float4*)&Bs[i >> 5][(i & 31) * 4] = w;
        }
        __syncthreads();
#pragma unroll
        for (int kk = 0; kk < 16; ++kk) {
            float a[8], b[8];
#pragma unroll
            for (int j = 0; j < 8; j++) a[j] = As[trow * 8 + j][kk];
#pragma unroll
            for (int j = 0; j < 8; j++) b[j] = Bs[kk][tcol * 8 + j];
#pragma unroll
            for (int i = 0; i < 8; i++)
#pragma unroll
                for (int j = 0; j < 8; j++)
                    acc[i][j] = fmaf(a[i], b[j], acc[i][j]);
        }
        __syncthreads();
    }

    float bias[8];
#pragma unroll
    for (int j = 0; j < 8; j++) bias[j] = __ldg(conv_b + tcol * 8 + j);

#pragma unroll
    for (int i = 0; i < 8; i++) {
        int gr = row0 + trow * 8 + i;
        if (gr < NN) {
            float4 r0 = make_float4(fmaxf(acc[i][0] + bias[0], 0.f),
                                    fmaxf(acc[i][1] + bias[1], 0.f),
                                    fmaxf(acc[i][2] + bias[2], 0.f),
                                    fmaxf(acc[i][3] + bias[3], 0.f));
            float4 r1 = make_float4(fmaxf(acc[i][4] + bias[4], 0.f),
                                    fmaxf(acc[i][5] + bias[5], 0.f),
                                    fmaxf(acc[i][6] + bias[6], 0.f),
                                    fmaxf(acc[i][7] + bias[7], 0.f));
            *(float4*)&out[(size_t)gr * DIM + tcol * 8] = r0;
            *(float4*)&out[(size_t)gr * DIM + tcol * 8 + 4] = r1;
        }
    }
}

// ---------------------------------------------------------------------------
extern "C" void kernel_launch(void* const* d_in, const int* in_sizes, int n_in,
                              void* d_out, int out_size) {
    const float* x        = (const float*)d_in[0];
    const void*  e0       = d_in[1];
    const void*  e1       = d_in[2];
    const float* W_rel    = (const float*)d_in[3];
    const float* W_self   = (const float*)d_in[4];
    const float* conv_w   = (const float*)d_in[5];
    const float* conv_b   = (const float*)d_in[6];
    float* out            = (float*)d_out;

    detect_kernel<<<1, 32>>>((const int*)e0);
    zero_kernel<<<(NN * DIM / 4 + 255) / 256, 256>>>();
    prep_kernel<<<(384 * 128 + 255) / 256, 256>>>(W_rel, W_self, conv_w);

    // 2*NE warps, 8 warps per 256-thread block
    int scatter_blocks = (2 * NE + 7) / 8;
    scatter_kernel<<<scatter_blocks, 256>>>(x, e0, e1);

    int gemm_blocks = (NN + 127) / 128;
    gemm1_kernel<<<gemm_blocks, 256>>>(x);
    gemm2_kernel<<<gemm_blocks, 256>>>(out, conv_b);
}

// round 4
// speedup vs baseline: 1.7360x; 1.7360x over previous
#include <cuda_runtime.h>
#include <stdint.h>

#define NN 100000
#define DIM 128
#define NE 600000

// Scratch (static device globals; no runtime allocation)
__device__ float g_S0[(size_t)NN * DIM];    // relation-0 feature sums
__device__ float g_S1[(size_t)NN * DIM];    // relation-1 feature sums
__device__ float g_agg[(size_t)NN * DIM];   // post-linear aggregate
__device__ float g_Wt[384 * 128];           // [k][o] tf32 concat of W0|W1|Wself
__device__ float g_Ct[384 * 128];           // [seg*128+c][o] tf32 conv weights
__device__ int   g_idx64;                   // 1 if edge indices are int64

__device__ __forceinline__ float tf32r(float f) {
    uint32_t u;
    asm("cvt.rna.tf32.f32 %0, %1;" : "=r"(u) : "f"(f));
    return __uint_as_float(u);
}

// ---------------------------------------------------------------------------
__global__ void zero_kernel() {
    size_t i = (size_t)blockIdx.x * blockDim.x + threadIdx.x;
    if (i < (size_t)NN * DIM / 4) {
        ((float4*)g_S0)[i] = make_float4(0.f, 0.f, 0.f, 0.f);
        ((float4*)g_S1)[i] = make_float4(0.f, 0.f, 0.f, 0.f);
    }
}

// Detect edge-index dtype: int64 values < 2^31 have all odd 32-bit words == 0.
__global__ void detect_kernel(const int* __restrict__ e0_raw) {
    if (threadIdx.x == 0 && blockIdx.x == 0) {
        int is64 = 1;
        for (int i = 1; i < 64; i += 2)
            if (e0_raw[i] != 0) { is64 = 0; break; }
        g_idx64 = is64;
    }
}

// Transpose/concat weights once per launch; pre-round to tf32.
__global__ void prep_kernel(const float* __restrict__ W_rel,
                            const float* __restrict__ W_self,
                            const float* __restrict__ conv_w) {
    int t = blockIdx.x * blockDim.x + threadIdx.x;
    if (t >= 384 * 128) return;
    int k = t >> 7, o = t & 127;
    int seg = k >> 7, kl = k & 127;
    float w = (seg < 2) ? W_rel[seg * 16384 + o * 128 + kl]
                        : W_self[o * 128 + kl];
    g_Wt[k * 128 + o] = tf32r(w);
    g_Ct[k * 128 + o] = tf32r(conv_w[o * 384 + kl * 3 + seg]);
}

// ---------------------------------------------------------------------------
// One warp handles one edge from EACH relation (MLP=2).
__global__ void scatter_kernel(const float* __restrict__ x,
                               const void* __restrict__ e0,
                               const void* __restrict__ e1) {
    int warp = (int)(((size_t)blockIdx.x * blockDim.x + threadIdx.x) >> 5);
    int lane = threadIdx.x & 31;
    if (warp >= NE) return;
    int s0, t0, s1, t1;
    if (g_idx64) {
        s0 = (int)((const long long*)e0)[warp];
        t0 = (int)((const long long*)e0)[NE + warp];
        s1 = (int)((const long long*)e1)[warp];
        t1 = (int)((const long long*)e1)[NE + warp];
    } else {
        s0 = ((const int*)e0)[warp];
        t0 = ((const int*)e0)[NE + warp];
        s1 = ((const int*)e1)[warp];
        t1 = ((const int*)e1)[NE + warp];
    }
    if ((unsigned)s0 < NN && (unsigned)t0 < NN) {
        float4 v = ((const float4*)(x + (size_t)s0 * DIM))[lane];
        float* dst = g_S0 + (size_t)t0 * DIM + lane * 4;
        asm volatile("red.global.add.v4.f32 [%0], {%1,%2,%3,%4};"
                     :: "l"(dst), "f"(v.x), "f"(v.y), "f"(v.z), "f"(v.w) : "memory");
    }
    if ((unsigned)s1 < NN && (unsigned)t1 < NN) {
        float4 v = ((const float4*)(x + (size_t)s1 * DIM))[lane];
        float* dst = g_S1 + (size_t)t1 * DIM + lane * 4;
        asm volatile("red.global.add.v4.f32 [%0], {%1,%2,%3,%4};"
                     :: "l"(dst), "f"(v.x), "f"(v.y), "f"(v.z), "f"(v.w) : "memory");
    }
}

// ---------------------------------------------------------------------------
// TF32 tensor-core GEMM. 128x128 CTA tile, 8 warps (4M x 2N) of 32x64,
// BK=32. mma.sync.m16n8k8.
// MODE 0: g_agg = [S0|S1|x] @ Wcat^T      (output via device symbol!)
// MODE 1: out  = relu(conv(agg) + b)      (A rows shifted by seg-1)
__device__ __forceinline__ void mma_tf32(float* d, const uint32_t* a,
                                         const uint32_t* b) {
    asm volatile(
        "mma.sync.aligned.m16n8k8.row.col.f32.tf32.tf32.f32 "
        "{%0,%1,%2,%3}, {%4,%5,%6,%7}, {%8,%9}, {%0,%1,%2,%3};"
        : "+f"(d[0]), "+f"(d[1]), "+f"(d[2]), "+f"(d[3])
        : "r"(a[0]), "r"(a[1]), "r"(a[2]), "r"(a[3]), "r"(b[0]), "r"(b[1]));
}

#define AS_STRIDE 36   // banks: m*4 + k  (injective per fragment load)
#define BS_STRIDE 136  // banks: k*8 + n  (injective per fragment load)

template <int MODE>
__global__ __launch_bounds__(256)
void gemm_tf32_kernel(const float* __restrict__ x,
                      const float* __restrict__ conv_b,
                      float* __restrict__ out) {
    __shared__ float As[128 * AS_STRIDE];
    __shared__ float Bs[32 * BS_STRIDE];
    const uint32_t* As_u = (const uint32_t*)As;
    const uint32_t* Bs_u = (const uint32_t*)Bs;

    int t = threadIdx.x, lane = t & 31, warp = t >> 5;
    int warpM = warp >> 1, warpN = warp & 1;
    int row0 = blockIdx.x * 128;
    int mrow = lane >> 2, kcol = lane & 3;

    float acc[2][8][4];
#pragma unroll
    for (int mt = 0; mt < 2; mt++)
#pragma unroll
        for (int nt = 0; nt < 8; nt++)
#pragma unroll
            for (int q = 0; q < 4; q++) acc[mt][nt][q] = 0.f;

    for (int kt = 0; kt < 12; ++kt) {
        int seg = kt >> 2, ko = (kt & 3) * 32;
        const float* Ab;
        int shift;
        if (MODE == 0) {
            Ab = (seg == 0) ? g_S0 : (seg == 1 ? g_S1 : x);
            shift = 0;
        } else {
            Ab = g_agg;
            shift = seg - 1;
        }
        // stage A (128x32), tf32-rounded
#pragma unroll
        for (int l = 0; l < 4; ++l) {
            int i = l * 256 + t;
            int r = i >> 3, kq = (i & 7) * 4;
            int gr = row0 + r + shift;
            float4 v = make_float4(0.f, 0.f, 0.f, 0.f);
            if (gr >= 0 && gr < NN)
                v = *(const float4*)(Ab + (size_t)gr * DIM + ko + kq);
            float4 w = make_float4(tf32r(v.x), tf32r(v.y), tf32r(v.z), tf32r(v.w));
            *(float4*)&As[r * AS_STRIDE + kq] = w;
        }
        // stage B (32x128), already tf32
        const float* Bsrc = (MODE == 0 ? g_Wt : g_Ct) + kt * 32 * 128;
#pragma unroll
        for (int l = 0; l < 4; ++l) {
            int i = l * 256 + t;
            int k = i >> 5, nq = (i & 31) * 4;
            *(float4*)&Bs[k * BS_STRIDE + nq] = *(const float4*)(Bsrc + k * 128 + nq);
        }
        __syncthreads();
#pragma unroll
        for (int kk = 0; kk < 4; ++kk) {
            int kb = kk * 8;
            uint32_t afr[2][4], bfr[8][2];
#pragma unroll
            for (int mt = 0; mt < 2; ++mt) {
                int m0 = warpM * 32 + mt * 16 + mrow;
                afr[mt][0] = As_u[m0 * AS_STRIDE + kb + kcol];
                afr[mt][1] = As_u[(m0 + 8) * AS_STRIDE + kb + kcol];
                afr[mt][2] = As_u[m0 * AS_STRIDE + kb + kcol + 4];
                afr[mt][3] = As_u[(m0 + 8) * AS_STRIDE + kb + kcol + 4];
            }
#pragma unroll
            for (int nt = 0; nt < 8; ++nt) {
                int n0 = warpN * 64 + nt * 8 + mrow;
                bfr[nt][0] = Bs_u[(kb + kcol) * BS_STRIDE + n0];
                bfr[nt][1] = Bs_u[(kb + kcol + 4) * BS_STRIDE + n0];
            }
#pragma unroll
            for (int mt = 0; mt < 2; ++mt)
#pragma unroll
                for (int nt = 0; nt < 8; ++nt)
                    mma_tf32(acc[mt][nt], afr[mt], bfr[nt]);
        }
        __syncthreads();
    }

    // epilogue: MODE 0 -> g_agg (device symbol), MODE 1 -> out (+bias, relu)
    float* Cout = (MODE == 0) ? g_agg : out;
    int ncol2 = (lane & 3) * 2;
    float2 bias[8];
    if (MODE == 1) {
#pragma unroll
        for (int nt = 0; nt < 8; ++nt) {
            int gc = warpN * 64 + nt * 8 + ncol2;
            bias[nt] = make_float2(__ldg(conv_b + gc), __ldg(conv_b + gc + 1));
        }
    }
#pragma unroll
    for (int mt = 0; mt < 2; ++mt) {
        int rbase = row0 + warpM * 32 + mt * 16 + mrow;
#pragma unroll
        for (int half = 0; half < 2; ++half) {
            int gr = rbase + half * 8;
            if (gr < NN) {
#pragma unroll
                for (int nt = 0; nt < 8; ++nt) {
                    int gc = warpN * 64 + nt * 8 + ncol2;
                    float v0 = acc[mt][nt][half * 2 + 0];
                    float v1 = acc[mt][nt][half * 2 + 1];
                    if (MODE == 1) {
                        v0 = fmaxf(v0 + bias[nt].x, 0.f);
                        v1 = fmaxf(v1 + bias[nt].y, 0.f);
                    }
                    *(float2*)&Cout[(size_t)gr * DIM + gc] = make_float2(v0, v1);
                }
            }
        }
    }
}

// ---------------------------------------------------------------------------
extern "C" void kernel_launch(void* const* d_in, const int* in_sizes, int n_in,
                              void* d_out, int out_size) {
    const float* x      = (const float*)d_in[0];
    const void*  e0     = d_in[1];
    const void*  e1     = d_in[2];
    const float* W_rel  = (const float*)d_in[3];
    const float* W_self = (const float*)d_in[4];
    const float* conv_w = (const float*)d_in[5];
    const float* conv_b = (const float*)d_in[6];
    float* out          = (float*)d_out;

    detect_kernel<<<1, 32>>>((const int*)e0);
    zero_kernel<<<(NN * DIM / 4 + 255) / 256, 256>>>();
    prep_kernel<<<(384 * 128 + 255) / 256, 256>>>(W_rel, W_self, conv_w);

    // NE warps, each handles 1 edge of each relation
    int scatter_blocks = (NE + 7) / 8;
    scatter_kernel<<<scatter_blocks, 256>>>(x, e0, e1);

    int gemm_blocks = (NN + 127) / 128;
    gemm_tf32_kernel<0><<<gemm_blocks, 256>>>(x, conv_b, out);
    gemm_tf32_kernel<1><<<gemm_blocks, 256>>>(x, conv_b, out);
}

// round 6
// speedup vs baseline: 2.1697x; 1.2498x over previous
#include <cuda_runtime.h>
#include <stdint.h>

#define NN 100000
#define DIM 128
#define NE 600000

// Scratch (static device globals; no runtime allocation)
__device__ float g_S0[(size_t)NN * DIM];    // relation-0 feature sums
__device__ float g_S1[(size_t)NN * DIM];    // relation-1 feature sums
__device__ float g_agg[(size_t)NN * DIM];   // post-linear aggregate
__device__ float g_Wt[384 * 128];           // [k][o] tf32 concat of W0|W1|Wself
__device__ float g_Ct[384 * 128];           // [seg*128+c][o] tf32 conv weights
__device__ int   g_idx64;                   // 1 if edge indices are int64

__device__ __forceinline__ float tf32r(float f) {
    uint32_t u;
    asm("cvt.rna.tf32.f32 %0, %1;" : "=r"(u) : "f"(f));
    return __uint_as_float(u);
}

// ---------------------------------------------------------------------------
// Zero S0/S1; block 0 thread 0 also detects the edge-index dtype
// (int64 node-ids < 2^31 have all odd 32-bit words == 0).
__global__ void zero_kernel(const int* __restrict__ e0_raw) {
    if (blockIdx.x == 0 && threadIdx.x == 0) {
        int is64 = 1;
        for (int i = 1; i < 64; i += 2)
            if (e0_raw[i] != 0) { is64 = 0; break; }
        g_idx64 = is64;
    }
    size_t i = (size_t)blockIdx.x * blockDim.x + threadIdx.x;
    if (i < (size_t)NN * DIM / 4) {
        ((float4*)g_S0)[i] = make_float4(0.f, 0.f, 0.f, 0.f);
        ((float4*)g_S1)[i] = make_float4(0.f, 0.f, 0.f, 0.f);
    }
}

// Transpose/concat weights once per launch; pre-round to tf32.
__global__ void prep_kernel(const float* __restrict__ W_rel,
                            const float* __restrict__ W_self,
                            const float* __restrict__ conv_w) {
    int t = blockIdx.x * blockDim.x + threadIdx.x;
    if (t >= 384 * 128) return;
    int k = t >> 7, o = t & 127;
    int seg = k >> 7, kl = k & 127;
    float w = (seg < 2) ? W_rel[seg * 16384 + o * 128 + kl]
                        : W_self[o * 128 + kl];
    g_Wt[k * 128 + o] = tf32r(w);
    g_Ct[k * 128 + o] = tf32r(conv_w[o * 384 + kl * 3 + seg]);
}

// ---------------------------------------------------------------------------
// One relation per launch: working set x + S = 102 MB < L2 (126 MB), so the
// random gathers and red.add stay L2-resident. One warp per edge.
template <int REL>
__global__ void scatter_one(const float* __restrict__ x,
                            const void* __restrict__ ei) {
    int warp = (int)(((size_t)blockIdx.x * blockDim.x + threadIdx.x) >> 5);
    int lane = threadIdx.x & 31;
    if (warp >= NE) return;
    float* S = (REL == 0) ? g_S0 : g_S1;
    int src, tgt;
    if (g_idx64) {
        src = (int)((const long long*)ei)[warp];
        tgt = (int)((const long long*)ei)[NE + warp];
    } else {
        src = ((const int*)ei)[warp];
        tgt = ((const int*)ei)[NE + warp];
    }
    if ((unsigned)src >= NN || (unsigned)tgt >= NN) return;
    float4 v = ((const float4*)(x + (size_t)src * DIM))[lane];
    float* dst = S + (size_t)tgt * DIM + lane * 4;
    asm volatile("red.global.add.v4.f32 [%0], {%1,%2,%3,%4};"
                 :: "l"(dst), "f"(v.x), "f"(v.y), "f"(v.z), "f"(v.w) : "memory");
}

// ---------------------------------------------------------------------------
// TF32 tensor-core GEMM, cp.async double-buffered. 128x128 CTA tile,
// 8 warps (4M x 2N) of 32x64, BK=32, mma.sync.m16n8k8.
// MODE 0: g_agg = [S0|S1|x] @ Wcat^T
// MODE 1: out  = relu(conv1d(agg) + b)   (A rows shifted by seg-1)
__device__ __forceinline__ void mma_tf32(float* d, const uint32_t* a,
                                         const uint32_t* b) {
    asm volatile(
        "mma.sync.aligned.m16n8k8.row.col.f32.tf32.tf32.f32 "
        "{%0,%1,%2,%3}, {%4,%5,%6,%7}, {%8,%9}, {%0,%1,%2,%3};"
        : "+f"(d[0]), "+f"(d[1]), "+f"(d[2]), "+f"(d[3])
        : "r"(a[0]), "r"(a[1]), "r"(a[2]), "r"(a[3]), "r"(b[0]), "r"(b[1]));
}

#define AS_STRIDE 36            // floats; 144B row pitch (16B-aligned)
#define BS_STRIDE 136           // floats; 544B row pitch (16B-aligned)
#define ASZ (128 * AS_STRIDE)   // 4608 floats per buffer
#define BSZ (32 * BS_STRIDE)    // 4352 floats per buffer
#define GEMM_SMEM ((2 * (ASZ + BSZ)) * sizeof(float))   // ~71.7 KB

__device__ __forceinline__ void cp16(float* dst, const float* src, bool valid) {
    uint32_t d = (uint32_t)__cvta_generic_to_shared(dst);
    int sz = valid ? 16 : 0;
    asm volatile("cp.async.ca.shared.global [%0], [%1], 16, %2;"
                 :: "r"(d), "l"(src), "r"(sz));
}

template <int MODE>
__global__ __launch_bounds__(256)
void gemm_tf32_kernel(const float* __restrict__ x,
                      const float* __restrict__ conv_b,
                      float* __restrict__ out) {
    extern __shared__ float sm[];
    float* As = sm;                    // [2][ASZ]
    float* Bs = sm + 2 * ASZ;          // [2][BSZ]

    int t = threadIdx.x, lane = t & 31, warp = t >> 5;
    int warpM = warp >> 1, warpN = warp & 1;
    int row0 = blockIdx.x * 128;
    int mrow = lane >> 2, kcol = lane & 3;

    float acc[2][8][4];
#pragma unroll
    for (int mt = 0; mt < 2; mt++)
#pragma unroll
        for (int nt = 0; nt < 8; nt++)
#pragma unroll
            for (int q = 0; q < 4; q++) acc[mt][nt][q] = 0.f;

    // stage K-tile kt into buffer kt&1 (raw fp32 A; pre-rounded tf32 B)
    auto stage = [&](int kt) {
        int seg = kt >> 2, ko = (kt & 3) * 32;
        const float* Ab;
        int shift;
        if (MODE == 0) {
            Ab = (seg == 0) ? g_S0 : (seg == 1 ? g_S1 : x);
            shift = 0;
        } else {
            Ab = g_agg;
            shift = seg - 1;
        }
        float* Asb = As + (kt & 1) * ASZ;
        float* Bsb = Bs + (kt & 1) * BSZ;
#pragma unroll
        for (int l = 0; l < 4; ++l) {
            int i = l * 256 + t;
            int r = i >> 3, kq = (i & 7) * 4;
            int gr = row0 + r + shift;
            bool valid = (gr >= 0 && gr < NN);
            const float* src = Ab + (size_t)(valid ? gr : 0) * DIM + ko + kq;
            cp16(&Asb[r * AS_STRIDE + kq], src, valid);
        }
        const float* Bsrc = (MODE == 0 ? g_Wt : g_Ct) + kt * 32 * 128;
#pragma unroll
        for (int l = 0; l < 4; ++l) {
            int i = l * 256 + t;
            int k = i >> 5, nq = (i & 31) * 4;
            cp16(&Bsb[k * BS_STRIDE + nq], Bsrc + k * 128 + nq, true);
        }
        asm volatile("cp.async.commit_group;");
    };

    stage(0);
    for (int kt = 0; kt < 12; ++kt) {
        if (kt < 11) {
            stage(kt + 1);
            asm volatile("cp.async.wait_group 1;");
        } else {
            asm volatile("cp.async.wait_group 0;");
        }
        __syncthreads();
        const uint32_t* As_u = (const uint32_t*)(As + (kt & 1) * ASZ);
        const uint32_t* Bs_u = (const uint32_t*)(Bs + (kt & 1) * BSZ);
#pragma unroll
        for (int kk = 0; kk < 4; ++kk) {
            int kb = kk * 8;
            uint32_t afr[2][4], bfr[8][2];
#pragma unroll
            for (int mt = 0; mt < 2; ++mt) {
                int m0 = warpM * 32 + mt * 16 + mrow;
                afr[mt][0] = As_u[m0 * AS_STRIDE + kb + kcol];
                afr[mt][1] = As_u[(m0 + 8) * AS_STRIDE + kb + kcol];
                afr[mt][2] = As_u[m0 * AS_STRIDE + kb + kcol + 4];
                afr[mt][3] = As_u[(m0 + 8) * AS_STRIDE + kb + kcol + 4];
                // round raw fp32 A fragments to tf32 in registers
#pragma unroll
                for (int q = 0; q < 4; ++q)
                    afr[mt][q] = __float_as_uint(tf32r(__uint_as_float(afr[mt][q])));
            }
#pragma unroll
            for (int nt = 0; nt < 8; ++nt) {
                int n0 = warpN * 64 + nt * 8 + mrow;
                bfr[nt][0] = Bs_u[(kb + kcol) * BS_STRIDE + n0];
                bfr[nt][1] = Bs_u[(kb + kcol + 4) * BS_STRIDE + n0];
            }
#pragma unroll
            for (int mt = 0; mt < 2; ++mt)
#pragma unroll
                for (int nt = 0; nt < 8; ++nt)
                    mma_tf32(acc[mt][nt], afr[mt], bfr[nt]);
        }
        __syncthreads();   // all reads done before buffer kt&1 is restaged
    }

    // epilogue: MODE 0 -> g_agg (device symbol), MODE 1 -> out (+bias, relu)
    float* Cout = (MODE == 0) ? g_agg : out;
    int ncol2 = (lane & 3) * 2;
    float2 bias[8];
    if (MODE == 1) {
#pragma unroll
        for (int nt = 0; nt < 8; ++nt) {
            int gc = warpN * 64 + nt * 8 + ncol2;
            bias[nt] = make_float2(__ldg(conv_b + gc), __ldg(conv_b + gc + 1));
        }
    }
#pragma unroll
    for (int mt = 0; mt < 2; ++mt) {
        int rbase = row0 + warpM * 32 + mt * 16 + mrow;
#pragma unroll
        for (int half = 0; half < 2; ++half) {
            int gr = rbase + half * 8;
            if (gr < NN) {
#pragma unroll
                for (int nt = 0; nt < 8; ++nt) {
                    int gc = warpN * 64 + nt * 8 + ncol2;
                    float v0 = acc[mt][nt][half * 2 + 0];
                    float v1 = acc[mt][nt][half * 2 + 1];
                    if (MODE == 1) {
                        v0 = fmaxf(v0 + bias[nt].x, 0.f);
                        v1 = fmaxf(v1 + bias[nt].y, 0.f);
                    }
                    *(float2*)&Cout[(size_t)gr * DIM + gc] = make_float2(v0, v1);
                }
            }
        }
    }
}

// ---------------------------------------------------------------------------
extern "C" void kernel_launch(void* const* d_in, const int* in_sizes, int n_in,
                              void* d_out, int out_size) {
    const float* x      = (const float*)d_in[0];
    const void*  e0     = d_in[1];
    const void*  e1     = d_in[2];
    const float* W_rel  = (const float*)d_in[3];
    const float* W_self = (const float*)d_in[4];
    const float* conv_w = (const float*)d_in[5];
    const float* conv_b = (const float*)d_in[6];
    float* out          = (float*)d_out;

    static bool attr_set = false;
    if (!attr_set) {
        cudaFuncSetAttribute(gemm_tf32_kernel<0>,
                             cudaFuncAttributeMaxDynamicSharedMemorySize, GEMM_SMEM);
        cudaFuncSetAttribute(gemm_tf32_kernel<1>,
                             cudaFuncAttributeMaxDynamicSharedMemorySize, GEMM_SMEM);
        attr_set = true;
    }

    zero_kernel<<<(NN * DIM / 4 + 255) / 256, 256>>>((const int*)e0);
    prep_kernel<<<(384 * 128 + 255) / 256, 256>>>(W_rel, W_self, conv_w);

    // relation-split scatter: each pass L2-resident (x + one S = 102 MB)
    int scatter_blocks = (NE + 7) / 8;
    scatter_one<0><<<scatter_blocks, 256>>>(x, e0);
    scatter_one<1><<<scatter_blocks, 256>>>(x, e1);

    int gemm_blocks = (NN + 127) / 128;
    gemm_tf32_kernel<0><<<gemm_blocks, 256, GEMM_SMEM>>>(x, conv_b, out);
    gemm_tf32_kernel<1><<<gemm_blocks, 256, GEMM_SMEM>>>(x, conv_b, out);
}